// round 13
// baseline (speedup 1.0000x reference)
#include <cuda_runtime.h>
#include <cuda_bf16.h>

// x shape (64, 20, 64, 32, 32) fp32 ; B=64, CHI=20, D=65536
#define B_    64
#define CHI_  20
#define D_    65536
#define WB_   8                    // batches per wave (41.9 MB -> L2 resident)
#define NW_   (B_ / WB_)           // 8 waves
#define SBLK_ 8                    // d-slice blocks per batch in scores pass
#define SLICE4_ 2048               // float4 per slice  (8192 floats, 32KB)

// Scratch (no cudaMalloc). g_part rows padded to 32 floats (128B) so writer
// blocks touch distinct cache lines.
__device__ float g_part[B_][SBLK_][32];  // partial scores per (batch, slice)
__device__ float g_alpha[B_][32];        // softmax weights

// ---------------------------------------------------------------------------
// scores pass (per wave): block = (b_local, d-slice). Loads last-row slice
// into REGISTERS once, then streams the 20 frames rows for that slice.
// Last-row LTS traffic: 32KB per block (vs 256KB x20 in the old version).
// ---------------------------------------------------------------------------
__global__ __launch_bounds__(256)
void scores_kernel(const float* __restrict__ x, int wave) {
    const int b_local = blockIdx.x >> 3;       // /SBLK_
    const int blk     = blockIdx.x & (SBLK_ - 1);
    const int b       = wave * WB_ + b_local;
    const size_t base = (size_t)b * CHI_ * D_;
    const int tid     = threadIdx.x;
    const int lane    = tid & 31;
    const int wid     = tid >> 5;

    // last-row slice -> registers (8 float4 per thread, coalesced)
    const float4* __restrict__ last4 =
        reinterpret_cast<const float4*>(x + base + (size_t)(CHI_ - 1) * D_)
        + blk * SLICE4_;
    float4 lr[8];
    #pragma unroll
    for (int i = 0; i < 8; i++)
        lr[i] = __ldg(last4 + tid + i * 256);

    // stream the 20 frames rows of this slice; dot against registers
    float acc[CHI_];
    #pragma unroll
    for (int c = 0; c < CHI_; c++) {
        const float4* __restrict__ f4 =
            reinterpret_cast<const float4*>(x + base + (size_t)c * D_)
            + blk * SLICE4_;
        float a = 0.0f;
        #pragma unroll
        for (int i = 0; i < 8; i++) {
            float4 v = __ldg(f4 + tid + i * 256);   // default policy: keep in L2
            a = fmaf(v.x, lr[i].x, a);
            a = fmaf(v.y, lr[i].y, a);
            a = fmaf(v.z, lr[i].z, a);
            a = fmaf(v.w, lr[i].w, a);
        }
        acc[c] = a;
    }

    // block reduction of 20 accumulators (fixed order -> deterministic)
    #pragma unroll
    for (int c = 0; c < CHI_; c++) {
        #pragma unroll
        for (int off = 16; off > 0; off >>= 1)
            acc[c] += __shfl_down_sync(0xFFFFFFFFu, acc[c], off);
    }
    __shared__ float s_red[8][CHI_];
    if (lane == 0) {
        #pragma unroll
        for (int c = 0; c < CHI_; c++) s_red[wid][c] = acc[c];
    }
    __syncthreads();
    if (tid < CHI_) {
        float v = 0.0f;
        #pragma unroll
        for (int w = 0; w < 8; w++) v += s_red[w][tid];
        g_part[b][blk][tid] = v;
    }
}

// ---------------------------------------------------------------------------
// alpha pass (per wave): one warp per batch; lane c sums the 8 slice
// partials in fixed order, then warp-softmax over 20 lanes.
// ---------------------------------------------------------------------------
__global__ __launch_bounds__(256)
void alpha_kernel(int wave) {
    const int wwarp = threadIdx.x >> 5;        // 0..7 -> batch within wave
    const int lane  = threadIdx.x & 31;
    const int b     = wave * WB_ + wwarp;

    float s = 0.0f;
    if (lane < CHI_) {
        #pragma unroll
        for (int blk = 0; blk < SBLK_; blk++)
            s += g_part[b][blk][lane];
        s *= (1.0f / (float)CHI_);
    }
    float sv = (lane < CHI_) ? s : -1e30f;
    #pragma unroll
    for (int off = 16; off > 0; off >>= 1)
        sv = fmaxf(sv, __shfl_xor_sync(0xFFFFFFFFu, sv, off));
    float e = (lane < CHI_) ? __expf(s - sv) : 0.0f;
    float z = e;
    #pragma unroll
    for (int off = 16; off > 0; off >>= 1)
        z += __shfl_xor_sync(0xFFFFFFFFu, z, off);
    if (lane < CHI_)
        g_alpha[b][lane] = e / z;
}

// ---------------------------------------------------------------------------
// out pass (per wave): out[b,d] = sum_c flat[b, d*20+c] * alpha[b,c]
// (transposed-view einsum; same cache lines scores just pulled into L2).
// ---------------------------------------------------------------------------
__global__ __launch_bounds__(256)
void out_kernel(const float* __restrict__ x, float* __restrict__ out, int wave) {
    __shared__ float alpha_s[CHI_];
    const int b = wave * WB_ + blockIdx.y;
    if (threadIdx.x < CHI_)
        alpha_s[threadIdx.x] = g_alpha[b][threadIdx.x];
    __syncthreads();

    const int d = blockIdx.x * 256 + threadIdx.x;   // gridDim.x = D/256
    const float4* __restrict__ p =
        reinterpret_cast<const float4*>(x + (size_t)b * CHI_ * D_ + (size_t)d * CHI_);

    float acc = 0.0f;
    #pragma unroll
    for (int j = 0; j < 5; j++) {
        float4 v = __ldg(p + j);                    // expected L2 hit
        acc = fmaf(v.x, alpha_s[j * 4 + 0], acc);
        acc = fmaf(v.y, alpha_s[j * 4 + 1], acc);
        acc = fmaf(v.z, alpha_s[j * 4 + 2], acc);
        acc = fmaf(v.w, alpha_s[j * 4 + 3], acc);
    }
    out[(size_t)b * D_ + d] = acc;
}

// ---------------------------------------------------------------------------
// Two-stream software pipeline inside the captured graph:
//   stream0 : scores(0) scores(1) scores(2) ... (scores(w) waits out(w-2))
//   s2      : alpha(0) out(0) alpha(1) out(1) ...
// scores(w+1) streams DRAM while out(w) drains L2. Throttle keeps <=2 waves
// (84 MB) live in L2. Stream/events created on the first (non-captured)
// correctness call; event record/wait are capture-legal.
// ---------------------------------------------------------------------------
extern "C" void kernel_launch(void* const* d_in, const int* in_sizes, int n_in,
                              void* d_out, int out_size) {
    const float* x   = (const float*)d_in[0];
    float*       out = (float*)d_out;

    static bool         init = false;
    static cudaStream_t s2;
    static cudaEvent_t  evS[NW_], evO[NW_];
    if (!init) {
        cudaStreamCreateWithFlags(&s2, cudaStreamNonBlocking);
        for (int i = 0; i < NW_; i++) {
            cudaEventCreateWithFlags(&evS[i], cudaEventDisableTiming);
            cudaEventCreateWithFlags(&evO[i], cudaEventDisableTiming);
        }
        init = true;
    }

    for (int w = 0; w < NW_; w++) {
        if (w >= 2)
            cudaStreamWaitEvent(0, evO[w - 2], 0);         // L2 residency throttle
        scores_kernel<<<WB_ * SBLK_, 256>>>(x, w);         // 64 blocks, stream 0
        cudaEventRecord(evS[w], 0);

        cudaStreamWaitEvent(s2, evS[w], 0);                // fork / dependency
        alpha_kernel<<<1, 256, 0, s2>>>(w);
        dim3 grid(D_ / 256, WB_);
        out_kernel<<<grid, 256, 0, s2>>>(x, out, w);
        cudaEventRecord(evO[w], s2);
    }
    cudaStreamWaitEvent(0, evO[NW_ - 1], 0);               // join
}

// round 14
// speedup vs baseline: 1.5084x; 1.5084x over previous
#include <cuda_runtime.h>
#include <cuda_bf16.h>

// x shape (64, 20, 64, 32, 32) fp32 ; B=64, CHI=20, D=65536
#define B_    64
#define CHI_  20
#define D_    65536
#define WB_   8                    // batches per wave (41.9 MB -> L2 resident)
#define NW_   (B_ / WB_)           // 8 waves
#define SBLK_ 64                   // d-slice blocks per batch (grid 512/wave)
#define SLICE4_ 256                // float4 per slice per row (1024 floats)

// Scratch (no cudaMalloc). g_part rows padded to 32 floats (128B) so writer
// blocks touch distinct cache lines.
__device__ float g_part[B_][SBLK_][32];  // partial scores per (batch, slice)
__device__ float g_alpha[B_][32];        // softmax weights

// ---------------------------------------------------------------------------
// scores pass (per wave): 512 blocks. Block = (b_local, d-slice of 1024
// floats). Thread holds its last-row float4 in a register, then issues 20
// INDEPENDENT row loads (MLP~20) accumulating into 20 separate chains.
// ---------------------------------------------------------------------------
__global__ __launch_bounds__(256)
void scores_kernel(const float* __restrict__ x, int wave) {
    const int b_local = blockIdx.x >> 6;        // / SBLK_
    const int blk     = blockIdx.x & (SBLK_ - 1);
    const int b       = wave * WB_ + b_local;
    const size_t base = (size_t)b * CHI_ * D_;
    const int tid     = threadIdx.x;
    const int lane    = tid & 31;
    const int wid     = tid >> 5;

    // last-row float4 for this thread's d position
    const int f4idx = blk * SLICE4_ + tid;      // float4 index within row
    const float4 lr = __ldg(
        reinterpret_cast<const float4*>(x + base + (size_t)(CHI_ - 1) * D_) + f4idx);

    // 20 independent dot contributions
    float acc[CHI_];
    #pragma unroll
    for (int c = 0; c < CHI_; c++) {
        float4 v = __ldg(
            reinterpret_cast<const float4*>(x + base + (size_t)c * D_) + f4idx);
        float a = v.x * lr.x;
        a = fmaf(v.y, lr.y, a);
        a = fmaf(v.z, lr.z, a);
        a = fmaf(v.w, lr.w, a);
        acc[c] = a;
    }

    // block reduction of 20 accumulators (fixed order -> deterministic)
    #pragma unroll
    for (int c = 0; c < CHI_; c++) {
        #pragma unroll
        for (int off = 16; off > 0; off >>= 1)
            acc[c] += __shfl_down_sync(0xFFFFFFFFu, acc[c], off);
    }
    __shared__ float s_red[8][CHI_];
    if (lane == 0) {
        #pragma unroll
        for (int c = 0; c < CHI_; c++) s_red[wid][c] = acc[c];
    }
    __syncthreads();
    if (tid < CHI_) {
        float v = 0.0f;
        #pragma unroll
        for (int w = 0; w < 8; w++) v += s_red[w][tid];
        g_part[b][blk][tid] = v;
    }
}

// ---------------------------------------------------------------------------
// alpha pass (per wave): one warp per batch; lane c sums the 64 slice
// partials in fixed order, then warp-softmax over 20 lanes.
// ---------------------------------------------------------------------------
__global__ __launch_bounds__(256)
void alpha_kernel(int wave) {
    const int wwarp = threadIdx.x >> 5;        // 0..7 -> batch within wave
    const int lane  = threadIdx.x & 31;
    const int b     = wave * WB_ + wwarp;

    float s = 0.0f;
    if (lane < CHI_) {
        #pragma unroll
        for (int blk = 0; blk < SBLK_; blk++)
            s += g_part[b][blk][lane];
        s *= (1.0f / (float)CHI_);
    }
    float sv = (lane < CHI_) ? s : -1e30f;
    #pragma unroll
    for (int off = 16; off > 0; off >>= 1)
        sv = fmaxf(sv, __shfl_xor_sync(0xFFFFFFFFu, sv, off));
    float e = (lane < CHI_) ? __expf(s - sv) : 0.0f;
    float z = e;
    #pragma unroll
    for (int off = 16; off > 0; off >>= 1)
        z += __shfl_xor_sync(0xFFFFFFFFu, z, off);
    if (lane < CHI_)
        g_alpha[b][lane] = e / z;
}

// ---------------------------------------------------------------------------
// out pass (per wave): out[b,d] = sum_c flat[b, d*20+c] * alpha[b,c]
// (transposed view; same cache lines the scores pass just pulled into L2).
// ---------------------------------------------------------------------------
__global__ __launch_bounds__(256)
void out_kernel(const float* __restrict__ x, float* __restrict__ out, int wave) {
    __shared__ float alpha_s[CHI_];
    const int b = wave * WB_ + blockIdx.y;
    if (threadIdx.x < CHI_)
        alpha_s[threadIdx.x] = g_alpha[b][threadIdx.x];
    __syncthreads();

    const int d = blockIdx.x * 256 + threadIdx.x;   // gridDim.x = D/256
    const float4* __restrict__ p =
        reinterpret_cast<const float4*>(x + (size_t)b * CHI_ * D_ + (size_t)d * CHI_);

    float acc = 0.0f;
    #pragma unroll
    for (int j = 0; j < 5; j++) {
        float4 v = __ldg(p + j);                    // expected L2 hit
        acc = fmaf(v.x, alpha_s[j * 4 + 0], acc);
        acc = fmaf(v.y, alpha_s[j * 4 + 1], acc);
        acc = fmaf(v.z, alpha_s[j * 4 + 2], acc);
        acc = fmaf(v.w, alpha_s[j * 4 + 3], acc);
    }
    out[(size_t)b * D_ + d] = acc;
}

// ---------------------------------------------------------------------------
// Two-stream pipeline inside the captured graph:
//   stream0 : scores(0) scores(1) ...   (scores(w) waits out(w-2))
//   s2      : alpha(0) out(0) alpha(1) out(1) ...
// scores(w+1) streams DRAM while out(w) drains L2; <=2 waves (84 MB) live.
// ---------------------------------------------------------------------------
extern "C" void kernel_launch(void* const* d_in, const int* in_sizes, int n_in,
                              void* d_out, int out_size) {
    const float* x   = (const float*)d_in[0];
    float*       out = (float*)d_out;

    static bool         init = false;
    static cudaStream_t s2;
    static cudaEvent_t  evS[NW_], evO[NW_];
    if (!init) {
        cudaStreamCreateWithFlags(&s2, cudaStreamNonBlocking);
        for (int i = 0; i < NW_; i++) {
            cudaEventCreateWithFlags(&evS[i], cudaEventDisableTiming);
            cudaEventCreateWithFlags(&evO[i], cudaEventDisableTiming);
        }
        init = true;
    }

    for (int w = 0; w < NW_; w++) {
        if (w >= 2)
            cudaStreamWaitEvent(0, evO[w - 2], 0);         // L2 residency throttle
        scores_kernel<<<WB_ * SBLK_, 256>>>(x, w);         // 512 blocks
        cudaEventRecord(evS[w], 0);

        cudaStreamWaitEvent(s2, evS[w], 0);                // fork / dependency
        alpha_kernel<<<1, 256, 0, s2>>>(w);
        dim3 grid(D_ / 256, WB_);
        out_kernel<<<grid, 256, 0, s2>>>(x, out, w);
        cudaEventRecord(evO[w], s2);
    }
    cudaStreamWaitEvent(0, evO[NW_ - 1], 0);               // join
}